// round 7
// baseline (speedup 1.0000x reference)
#include <cuda_runtime.h>
#include <cuda_bf16.h>
#include <math.h>
#include <stdint.h>

#define Bdim 4
#define Tdim 512
#define Hdim 32
#define Ndim 64
#define Ddim 2048           // Hdim*Ndim
#define Mtot (Bdim*Tdim)    // 2048
#define Ktot Ddim           // 2048

// ---------------- device scratch (no allocs allowed) ----------------
__device__ float          g_d [Bdim * Tdim * Ddim];   // decay
__device__ float          g_kk[Bdim * Tdim * Ddim];   // normalized k
__device__ float          g_bb[Bdim * Tdim * Ddim];   // kk * sigmoid(iclr)
__device__ __nv_bfloat16  g_Ahi[Mtot * Ktot];         // y hi (bf16)
__device__ __nv_bfloat16  g_Alo[Mtot * Ktot];         // y lo (bf16)
__device__ __nv_bfloat16  g_Wb [Ddim * Ktot];         // W (bf16, exact)

// ---------------- PTX helpers (plain sm_80+ features only) ----------------
__device__ __forceinline__ uint32_t smem_u32(const void* p) {
    return (uint32_t)__cvta_generic_to_shared(p);
}
__device__ __forceinline__ void cp_async16(uint32_t smaddr, const void* g) {
    asm volatile("cp.async.cg.shared.global [%0], [%1], 16;" :: "r"(smaddr), "l"(g));
}
#define CP_COMMIT() asm volatile("cp.async.commit_group;" ::: "memory")
#define CP_WAIT(n)  asm volatile("cp.async.wait_group %0;" :: "n"(n) : "memory")

__device__ __forceinline__ void bar_named(int id) {
    asm volatile("bar.sync %0, %1;" :: "r"(id), "r"(256) : "memory");
}
__device__ __forceinline__ void ldsm_x4(uint32_t* r, uint32_t addr) {
    asm volatile("ldmatrix.sync.aligned.m8n8.x4.shared.b16 {%0,%1,%2,%3}, [%4];"
        : "=r"(r[0]), "=r"(r[1]), "=r"(r[2]), "=r"(r[3]) : "r"(addr));
}
__device__ __forceinline__ void mma_bf16(float* d, const uint32_t* a, const uint32_t* b) {
    asm volatile("mma.sync.aligned.m16n8k16.row.col.f32.bf16.bf16.f32 "
        "{%0,%1,%2,%3}, {%4,%5,%6,%7}, {%8,%9}, {%0,%1,%2,%3};"
        : "+f"(d[0]), "+f"(d[1]), "+f"(d[2]), "+f"(d[3])
        : "r"(a[0]), "r"(a[1]), "r"(a[2]), "r"(a[3]), "r"(b[0]), "r"(b[1]));
}

// ---------------------------------------------------------------------------
// Kernel 0a: elementwise precompute (decay, kk, b)
// ---------------------------------------------------------------------------
__global__ void __launch_bounds__(256) wkv7_pre_kernel(
    const float* __restrict__ w, const float* __restrict__ k,
    const float* __restrict__ iclr)
{
    const int vec  = blockIdx.x * 8 + (threadIdx.x >> 5);
    const int lane = threadIdx.x & 31;
    const size_t base = (size_t)vec * Ndim;

    float k0 = k[base + lane], k1 = k[base + lane + 32];
    float p = fmaf(k0, k0, k1 * k1);
#pragma unroll
    for (int o = 16; o; o >>= 1) p += __shfl_xor_sync(0xffffffffu, p, o);
    const float inv = rsqrtf(p + 1e-12f);

    float w0 = w[base + lane], w1 = w[base + lane + 32];
    float c0 = iclr[base + lane], c1 = iclr[base + lane + 32];

    g_d[base + lane]      = __expf(-__expf(w0));
    g_d[base + lane + 32] = __expf(-__expf(w1));
    const float kk0 = k0 * inv, kk1 = k1 * inv;
    g_kk[base + lane]      = kk0;
    g_kk[base + lane + 32] = kk1;
    g_bb[base + lane]      = kk0 / (1.0f + __expf(-c0));
    g_bb[base + lane + 32] = kk1 / (1.0f + __expf(-c1));
}

// ---------------------------------------------------------------------------
// Kernel 0b: Wq (int32) -> bf16 (exact, |v|<=128)
// ---------------------------------------------------------------------------
__global__ void __launch_bounds__(256) wconv_kernel(const int* __restrict__ wq)
{
    const size_t i4 = (size_t)blockIdx.x * 256 + threadIdx.x;   // int4 index
    int4 q = ((const int4*)wq)[i4];
    __nv_bfloat16 o[4];
    o[0] = __float2bfloat16((float)q.x);
    o[1] = __float2bfloat16((float)q.y);
    o[2] = __float2bfloat16((float)q.z);
    o[3] = __float2bfloat16((float)q.w);
    *(uint2*)&g_Wb[i4 * 4] = *(uint2*)o;
}

// ---------------------------------------------------------------------------
// Kernel 1: WKV scan. 512 threads = 2 independent (b,h) streams per block,
// each with its own named barrier + 16-slot cp.async ring.
// One commit group per 4-step superstep; wait_group 2 => ~3 supersteps of
// prefetch depth. Loader lanes spread across all 8 warps (12 lanes each).
// Per stream: row = htid>>2, seg = htid&3, 16 fp32 state regs/thread.
// ---------------------------------------------------------------------------
__global__ void __launch_bounds__(512) wkv7_scan_kernel(
    const float* __restrict__ r, const float* __restrict__ k,
    const float* __restrict__ v)
{
    const int tid  = threadIdx.x;
    const int half = tid >> 8;              // stream 0/1
    const int htid = tid & 255;
    const int bh   = blockIdx.x * 2 + half;
    const int b    = bh >> 5;
    const int h    = bh & 31;
    const int row  = htid >> 2;
    const int seg  = htid & 3;
    const int jb   = seg * 16;
    const int barid = half + 1;

    // per stream: 16 slots x 384 floats
    // slot layout: d[0,64) kk[64,128) b[128,192) k[192,256) r[256,320) v[320,384)
    __shared__ __align__(16) float sbuf[2][16][6 * Ndim];

    float state[16];
#pragma unroll
    for (int c = 0; c < 16; c++) state[c] = 0.f;

    // loader mapping: each warp contributes lanes 0..11 -> 8*12 = 96 loaders
    const int wl   = htid >> 5;
    const int lane = htid & 31;
    const bool is_loader = (lane < 12);
    const int lidx = wl * 12 + lane;        // 0..95 when is_loader
    const int lvec = lidx >> 4;             // 0..5
    const int lq   = lidx & 15;             // 0..15
    const size_t vstep = (size_t)Hdim * Ndim / 4;   // float4 per t

    const float4* gbase = nullptr;
    uint32_t sdst = 0;
    if (is_loader) {
        const float* sp;
        switch (lvec) {
            case 0: sp = g_d;  break;
            case 1: sp = g_kk; break;
            case 2: sp = g_bb; break;
            case 3: sp = k;    break;
            case 4: sp = r;    break;
            default: sp = v;   break;
        }
        gbase = (const float4*)sp + (((size_t)b * Tdim) * Hdim + h) * (Ndim / 4) + lq;
        sdst  = smem_u32(&sbuf[half][0][0]) + lidx * 16;
    }

    // prologue: supersteps 0..2 (steps 0..11), one commit group each
#pragma unroll
    for (int ss = 0; ss < 3; ss++) {
        if (is_loader) {
#pragma unroll
            for (int u = 0; u < 4; u++) {
                const int st = ss * 4 + u;
                cp_async16(sdst + (st & 15) * (6 * Ndim * 4), gbase + (size_t)st * vstep);
            }
        }
        CP_COMMIT();
    }

    size_t ybase = ((size_t)b * Tdim) * Ddim + h * Ndim + row;

    for (int t0 = 0; t0 < Tdim; t0 += 4) {
        CP_WAIT(2);                 // steps t0..t0+3 landed (issued 3 supersteps ago)
        bar_named(barid);           // publish within this stream only

        // issue superstep t0+12 .. t0+15
        if (is_loader) {
#pragma unroll
            for (int u = 0; u < 4; u++) {
                const int st = t0 + 12 + u;
                if (st < Tdim)
                    cp_async16(sdst + (st & 15) * (6 * Ndim * 4), gbase + (size_t)st * vstep);
            }
        }
        CP_COMMIT();

        // 4 compute steps, no barriers between them
#pragma unroll
        for (int u = 0; u < 4; u++) {
            const int t = t0 + u;
            const float* s = sbuf[half][t & 15];
            const float4* d4  = (const float4*)(s +   0 + jb);
            const float4* kk4 = (const float4*)(s +  64 + jb);
            const float4* b4  = (const float4*)(s + 128 + jb);
            const float4* k4  = (const float4*)(s + 192 + jb);
            const float4* r4  = (const float4*)(s + 256 + jb);
            const float vv = s[320 + row];

            float p0 = 0.f, p1 = 0.f, p2 = 0.f, p3 = 0.f;
#pragma unroll
            for (int q = 0; q < 4; q++) {
                float4 kv = kk4[q];
                p0 = fmaf(state[4*q+0], kv.x, p0);
                p1 = fmaf(state[4*q+1], kv.y, p1);
                p2 = fmaf(state[4*q+2], kv.z, p2);
                p3 = fmaf(state[4*q+3], kv.w, p3);
            }
            float sa_p = (p0 + p1) + (p2 + p3);
            sa_p += __shfl_xor_sync(0xffffffffu, sa_p, 1);
            sa_p += __shfl_xor_sync(0xffffffffu, sa_p, 2);
            const float sa = -sa_p;

            float y0 = 0.f, y1 = 0.f, y2 = 0.f, y3 = 0.f;
#pragma unroll
            for (int q = 0; q < 4; q++) {
                float4 dd = d4[q], bb = b4[q], kq = k4[q], rr = r4[q];
                float t0f = fmaf(sa, bb.x, vv * kq.x);
                float t1f = fmaf(sa, bb.y, vv * kq.y);
                float t2f = fmaf(sa, bb.z, vv * kq.z);
                float t3f = fmaf(sa, bb.w, vv * kq.w);
                state[4*q+0] = fmaf(state[4*q+0], dd.x, t0f);
                state[4*q+1] = fmaf(state[4*q+1], dd.y, t1f);
                state[4*q+2] = fmaf(state[4*q+2], dd.z, t2f);
                state[4*q+3] = fmaf(state[4*q+3], dd.w, t3f);
                y0 = fmaf(state[4*q+0], rr.x, y0);
                y1 = fmaf(state[4*q+1], rr.y, y1);
                y2 = fmaf(state[4*q+2], rr.z, y2);
                y3 = fmaf(state[4*q+3], rr.w, y3);
            }
            float yp = (y0 + y1) + (y2 + y3);
            yp += __shfl_xor_sync(0xffffffffu, yp, 1);
            yp += __shfl_xor_sync(0xffffffffu, yp, 2);
            if (seg == 0) {
                const size_t yi = ybase + (size_t)t * Ddim;
                __nv_bfloat16 hi = __float2bfloat16(yp);
                g_Ahi[yi] = hi;
                g_Alo[yi] = __float2bfloat16(yp - __bfloat162float(hi));
            }
        }
    }
}

// ---------------------------------------------------------------------------
// Kernel 2: mma.sync bf16 split GEMM (NT) — R5 config (2-stage, 96KB).
// 128x128 tile, BK=64, 8 warps (2x4), warp tile 64x32, SW128 swizzle.
// out[m,o] = scale[o] * (Ahi[m,:]+Alo[m,:]) . Wb[o,:]
// ---------------------------------------------------------------------------
#define NCH   (Ktot / 64)          // 32 K-chunks
#define STAGE 49152                // 3 tiles * 16KB
#define GSM_TOTAL (2 * STAGE)

__device__ __forceinline__ uint32_t swz(uint32_t row, uint32_t cbyte) {
    uint32_t off = row * 128 + cbyte;
    return off ^ ((off >> 3) & 0x70);
}

__global__ void __launch_bounds__(256) mma_gemm_kernel(
    const float* __restrict__ scale, float* __restrict__ out)
{
    extern __shared__ __align__(1024) char smem[];
    const uint32_t sb = smem_u32(smem);
    const int tid  = threadIdx.x;
    const int wid  = tid >> 5;
    const int lane = tid & 31;
    const int bm = blockIdx.y * 128;
    const int bn = blockIdx.x * 128;

    const int mbase = (wid >> 2) * 64;      // 0 / 64
    const int nbase = (wid & 3) * 32;       // 0/32/64/96

    auto load_stage = [&](int c, int p) {
        const uint32_t base = sb + p * STAGE;
        const size_t kof = (size_t)c * 64;
#pragma unroll
        for (int it = 0; it < 12; it++) {
            const int id   = tid + it * 256;        // 0..3071
            const int tile = id >> 10;              // 0:Ahi 1:Alo 2:W
            const int rem  = id & 1023;
            const int rw   = rem >> 3;              // row 0..127
            const int c8   = rem & 7;               // 16B chunk
            const uint32_t sa = base + tile * 16384 + swz(rw, c8 * 16);
            const __nv_bfloat16* g =
                (tile == 0) ? g_Ahi + (size_t)(bm + rw) * Ktot + kof + c8 * 8 :
                (tile == 1) ? g_Alo + (size_t)(bm + rw) * Ktot + kof + c8 * 8 :
                              g_Wb  + (size_t)(bn + rw) * Ktot + kof + c8 * 8;
            cp_async16(sa, g);
        }
    };

    float acc[4][4][4];
#pragma unroll
    for (int i = 0; i < 4; i++)
#pragma unroll
        for (int j = 0; j < 4; j++)
#pragma unroll
            for (int q = 0; q < 4; q++) acc[i][j][q] = 0.f;

    const uint32_t rowAl = lane & 15;
    const uint32_t cexA  = (lane >> 4) * 16;
    const uint32_t rowBl = ((lane >> 4) << 3) + (lane & 7);
    const uint32_t cexB  = ((lane >> 3) & 1) * 16;

    load_stage(0, 0);
    CP_COMMIT();

    for (int c = 0; c < NCH; c++) {
        const int p = c & 1;
        if (c + 1 < NCH) {
            load_stage(c + 1, p ^ 1);
            CP_COMMIT();
            CP_WAIT(1);
        } else {
            CP_WAIT(0);
        }
        __syncthreads();

        const uint32_t aB = sb + p * STAGE;          // Ahi
        const uint32_t lB = aB + 16384;               // Alo
        const uint32_t wB = aB + 32768;               // W

#pragma unroll
        for (int ks = 0; ks < 4; ks++) {
            const uint32_t kca = ks * 32 + cexA;
            const uint32_t kcb = ks * 32 + cexB;
            uint32_t bq[4][2];
            {
                uint32_t t[4];
                ldsm_x4(t, wB + swz(nbase + rowBl, kcb));
                bq[0][0] = t[0]; bq[0][1] = t[1]; bq[1][0] = t[2]; bq[1][1] = t[3];
                ldsm_x4(t, wB + swz(nbase + 16 + rowBl, kcb));
                bq[2][0] = t[0]; bq[2][1] = t[1]; bq[3][0] = t[2]; bq[3][1] = t[3];
            }
            uint32_t ah[4][4], al[4][4];
#pragma unroll
            for (int im = 0; im < 4; im++) {
                ldsm_x4(ah[im], aB + swz(mbase + im * 16 + rowAl, kca));
                ldsm_x4(al[im], lB + swz(mbase + im * 16 + rowAl, kca));
            }
#pragma unroll
            for (int im = 0; im < 4; im++)
#pragma unroll
                for (int in = 0; in < 4; in++) {
                    mma_bf16(acc[im][in], ah[im], bq[in]);
                    mma_bf16(acc[im][in], al[im], bq[in]);
                }
        }
        __syncthreads();
    }

    // ---- epilogue ----
    const int gid = lane >> 2;
    const int tig = lane & 3;
#pragma unroll
    for (int in = 0; in < 4; in++) {
        const int col = bn + nbase + in * 8 + tig * 2;
        const float s0 = scale[col], s1 = scale[col + 1];
#pragma unroll
        for (int im = 0; im < 4; im++) {
            const int row0 = bm + mbase + im * 16 + gid;
            float2 o0, o1;
            o0.x = acc[im][in][0] * s0; o0.y = acc[im][in][1] * s1;
            o1.x = acc[im][in][2] * s0; o1.y = acc[im][in][3] * s1;
            *(float2*)&out[(size_t)row0 * Ddim + col]       = o0;
            *(float2*)&out[(size_t)(row0 + 8) * Ddim + col] = o1;
        }
    }
}

// ---------------------------------------------------------------------------
extern "C" void kernel_launch(void* const* d_in, const int* in_sizes, int n_in,
                              void* d_out, int out_size)
{
    const float* r     = (const float*)d_in[0];
    const float* w     = (const float*)d_in[1];
    const float* k     = (const float*)d_in[2];
    const float* v     = (const float*)d_in[3];
    const float* iclr  = (const float*)d_in[4];
    const int*   wq    = (const int*)d_in[5];
    const float* wsc   = (const float*)d_in[6];
    float* out = (float*)d_out;

    wkv7_pre_kernel<<<Bdim * Tdim * Hdim / 8, 256>>>(w, k, iclr);
    wconv_kernel<<<(Ddim * Ktot) / 1024, 256>>>(wq);
    wkv7_scan_kernel<<<Bdim * Hdim / 2, 512>>>(r, k, v);

    static int smem_set = 0;
    if (!smem_set) {
        cudaFuncSetAttribute(mma_gemm_kernel,
                             cudaFuncAttributeMaxDynamicSharedMemorySize, GSM_TOTAL);
        smem_set = 1;
    }
    dim3 grid(Ddim / 128, Mtot / 128);
    mma_gemm_kernel<<<grid, 256, GSM_TOTAL>>>(wsc, out);
}

// round 8
// speedup vs baseline: 2.2970x; 2.2970x over previous
#include <cuda_runtime.h>
#include <cuda_bf16.h>
#include <math.h>
#include <stdint.h>

#define Bdim 4
#define Tdim 512
#define Hdim 32
#define Ndim 64
#define Ddim 2048           // Hdim*Ndim
#define Mtot (Bdim*Tdim)    // 2048
#define Ktot Ddim           // 2048

// ---------------- device scratch (no allocs allowed) ----------------
__device__ float          g_d [Bdim * Tdim * Ddim];   // decay
__device__ float          g_kk[Bdim * Tdim * Ddim];   // normalized k
__device__ float          g_bb[Bdim * Tdim * Ddim];   // kk * sigmoid(iclr)
__device__ __nv_bfloat16  g_Ahi[Mtot * Ktot];         // y hi (bf16)
__device__ __nv_bfloat16  g_Alo[Mtot * Ktot];         // y lo (bf16)
__device__ __nv_bfloat16  g_Wb [Ddim * Ktot];         // W (bf16, exact)

// ---------------- PTX helpers (plain sm_80+ features only) ----------------
__device__ __forceinline__ uint32_t smem_u32(const void* p) {
    return (uint32_t)__cvta_generic_to_shared(p);
}
__device__ __forceinline__ void cp_async16(uint32_t smaddr, const void* g) {
    asm volatile("cp.async.cg.shared.global [%0], [%1], 16;" :: "r"(smaddr), "l"(g));
}
#define CP_COMMIT() asm volatile("cp.async.commit_group;" ::: "memory")
#define CP_WAIT(n)  asm volatile("cp.async.wait_group %0;" :: "n"(n) : "memory")

__device__ __forceinline__ void ldsm_x4(uint32_t* r, uint32_t addr) {
    asm volatile("ldmatrix.sync.aligned.m8n8.x4.shared.b16 {%0,%1,%2,%3}, [%4];"
        : "=r"(r[0]), "=r"(r[1]), "=r"(r[2]), "=r"(r[3]) : "r"(addr));
}
__device__ __forceinline__ void mma_bf16(float* d, const uint32_t* a, const uint32_t* b) {
    asm volatile("mma.sync.aligned.m16n8k16.row.col.f32.bf16.bf16.f32 "
        "{%0,%1,%2,%3}, {%4,%5,%6,%7}, {%8,%9}, {%0,%1,%2,%3};"
        : "+f"(d[0]), "+f"(d[1]), "+f"(d[2]), "+f"(d[3])
        : "r"(a[0]), "r"(a[1]), "r"(a[2]), "r"(a[3]), "r"(b[0]), "r"(b[1]));
}

// ---------------------------------------------------------------------------
// Kernel 0a: elementwise precompute (decay, kk, b)
// ---------------------------------------------------------------------------
__global__ void __launch_bounds__(256) wkv7_pre_kernel(
    const float* __restrict__ w, const float* __restrict__ k,
    const float* __restrict__ iclr)
{
    const int vec  = blockIdx.x * 8 + (threadIdx.x >> 5);
    const int lane = threadIdx.x & 31;
    const size_t base = (size_t)vec * Ndim;

    float k0 = k[base + lane], k1 = k[base + lane + 32];
    float p = fmaf(k0, k0, k1 * k1);
#pragma unroll
    for (int o = 16; o; o >>= 1) p += __shfl_xor_sync(0xffffffffu, p, o);
    const float inv = rsqrtf(p + 1e-12f);

    float w0 = w[base + lane], w1 = w[base + lane + 32];
    float c0 = iclr[base + lane], c1 = iclr[base + lane + 32];

    g_d[base + lane]      = __expf(-__expf(w0));
    g_d[base + lane + 32] = __expf(-__expf(w1));
    const float kk0 = k0 * inv, kk1 = k1 * inv;
    g_kk[base + lane]      = kk0;
    g_kk[base + lane + 32] = kk1;
    g_bb[base + lane]      = kk0 / (1.0f + __expf(-c0));
    g_bb[base + lane + 32] = kk1 / (1.0f + __expf(-c1));
}

// ---------------------------------------------------------------------------
// Kernel 0b: Wq (int32) -> bf16 (exact, |v|<=128)
// ---------------------------------------------------------------------------
__global__ void __launch_bounds__(256) wconv_kernel(const int* __restrict__ wq)
{
    const size_t i4 = (size_t)blockIdx.x * 256 + threadIdx.x;   // int4 index
    int4 q = ((const int4*)wq)[i4];
    __nv_bfloat16 o[4];
    o[0] = __float2bfloat16((float)q.x);
    o[1] = __float2bfloat16((float)q.y);
    o[2] = __float2bfloat16((float)q.z);
    o[3] = __float2bfloat16((float)q.w);
    *(uint2*)&g_Wb[i4 * 4] = *(uint2*)o;
}

// ---------------------------------------------------------------------------
// Kernel 1: WKV scan. One block (256 thr) per (b,h).
// Layout: seg = tid&7 (8 cols each), rp = tid>>3 -> rows {2rp, 2rp+1}.
// Each thread: 16 fp32 state regs (2 rows x 8 cols), 10 LDS.128 operand
// loads per step (amortized over both rows). Reductions: 3 shfl over 8 lanes.
// 8-slot cp.async ring, one commit group per 4-step superstep (depth 1
// superstep ~ thousands of cycles), ONE barrier per 4 steps.
// ---------------------------------------------------------------------------
__global__ void __launch_bounds__(256) wkv7_scan_kernel(
    const float* __restrict__ r, const float* __restrict__ k,
    const float* __restrict__ v)
{
    const int bh = blockIdx.x;          // 0..127
    const int b  = bh >> 5;
    const int h  = bh & 31;
    const int tid = threadIdx.x;
    const int seg = tid & 7;            // 0..7 (8-col segment)
    const int rp  = tid >> 3;           // 0..31 (row pair)
    const int row0 = rp * 2;
    const int jb  = seg * 8;            // column base

    // ring: 8 step-slots; slot layout:
    // d[0,64) kk[64,128) b[128,192) k[192,256) r[256,320) v[320,384)
    __shared__ __align__(16) float sbuf[8][6 * Ndim];

    float sA[8], sB[8];
#pragma unroll
    for (int c = 0; c < 8; c++) { sA[c] = 0.f; sB[c] = 0.f; }

    // loader mapping: lanes 0..11 of each warp -> 96 loaders, 1 float4 each
    const int wl   = tid >> 5;
    const int lane = tid & 31;
    const bool is_loader = (lane < 12);
    const int lidx = wl * 12 + lane;        // 0..95
    const int lvec = lidx >> 4;             // 0..5
    const int lq   = lidx & 15;             // 0..15
    const size_t vstep = (size_t)Hdim * Ndim / 4;   // float4 per t

    const float4* gbase = nullptr;
    uint32_t sdst = 0;
    if (is_loader) {
        const float* sp;
        switch (lvec) {
            case 0: sp = g_d;  break;
            case 1: sp = g_kk; break;
            case 2: sp = g_bb; break;
            case 3: sp = k;    break;
            case 4: sp = r;    break;
            default: sp = v;   break;
        }
        gbase = (const float4*)sp + (((size_t)b * Tdim) * Hdim + h) * (Ndim / 4) + lq;
        sdst  = smem_u32(&sbuf[0][0]) + lidx * 16;
    }
    const uint32_t slot_bytes = 6 * Ndim * 4;   // 1536

    // prologue: issue superstep 0 (steps 0..3)
    if (is_loader) {
#pragma unroll
        for (int u = 0; u < 4; u++)
            cp_async16(sdst + (u & 7) * slot_bytes, gbase + (size_t)u * vstep);
    }
    CP_COMMIT();

    const size_t ybase = ((size_t)b * Tdim) * Ddim + h * Ndim + row0;

    for (int t0 = 0; t0 < Tdim; t0 += 4) {
        CP_WAIT(0);                 // superstep t0 landed (issued 1 superstep ago)
        __syncthreads();

        // issue superstep t0+4 .. t0+7
        if (is_loader) {
#pragma unroll
            for (int u = 0; u < 4; u++) {
                const int st = t0 + 4 + u;
                if (st < Tdim)
                    cp_async16(sdst + (st & 7) * slot_bytes, gbase + (size_t)st * vstep);
            }
        }
        CP_COMMIT();

        // 4 compute steps, no barriers between them
#pragma unroll
        for (int u = 0; u < 4; u++) {
            const int t = t0 + u;
            const float* s = sbuf[t & 7];

            float4 d0  = *(const float4*)(s +   0 + jb);
            float4 d1  = *(const float4*)(s +   4 + jb);
            float4 q0  = *(const float4*)(s +  64 + jb);   // kk
            float4 q1  = *(const float4*)(s +  68 + jb);
            float4 b0  = *(const float4*)(s + 128 + jb);
            float4 b1  = *(const float4*)(s + 132 + jb);
            float4 k0  = *(const float4*)(s + 192 + jb);
            float4 k1  = *(const float4*)(s + 196 + jb);
            float4 r0  = *(const float4*)(s + 256 + jb);
            float4 r1  = *(const float4*)(s + 260 + jb);
            const float vA = s[320 + row0];
            const float vB = s[320 + row0 + 1];

            // sa = -dot(state_row, kk), per row, reduced over 8 seg lanes
            float pa = sA[0]*q0.x + sA[1]*q0.y + sA[2]*q0.z + sA[3]*q0.w
                     + sA[4]*q1.x + sA[5]*q1.y + sA[6]*q1.z + sA[7]*q1.w;
            float pb = sB[0]*q0.x + sB[1]*q0.y + sB[2]*q0.z + sB[3]*q0.w
                     + sB[4]*q1.x + sB[5]*q1.y + sB[6]*q1.z + sB[7]*q1.w;
            pa += __shfl_xor_sync(0xffffffffu, pa, 1);
            pb += __shfl_xor_sync(0xffffffffu, pb, 1);
            pa += __shfl_xor_sync(0xffffffffu, pa, 2);
            pb += __shfl_xor_sync(0xffffffffu, pb, 2);
            pa += __shfl_xor_sync(0xffffffffu, pa, 4);
            pb += __shfl_xor_sync(0xffffffffu, pb, 4);
            const float saA = -pa, saB = -pb;

            // state = state*d + sa*b + v*k ; y partial = dot(state, r)
            const float dd[8] = {d0.x,d0.y,d0.z,d0.w,d1.x,d1.y,d1.z,d1.w};
            const float bb[8] = {b0.x,b0.y,b0.z,b0.w,b1.x,b1.y,b1.z,b1.w};
            const float kq[8] = {k0.x,k0.y,k0.z,k0.w,k1.x,k1.y,k1.z,k1.w};
            const float rr[8] = {r0.x,r0.y,r0.z,r0.w,r1.x,r1.y,r1.z,r1.w};

            float yA = 0.f, yB = 0.f;
#pragma unroll
            for (int j = 0; j < 8; j++) {
                float vk = vA * kq[j];
                float tA = fmaf(saA, bb[j], vk);
                sA[j] = fmaf(sA[j], dd[j], tA);
                yA = fmaf(sA[j], rr[j], yA);
                float vk2 = vB * kq[j];
                float tB = fmaf(saB, bb[j], vk2);
                sB[j] = fmaf(sB[j], dd[j], tB);
                yB = fmaf(sB[j], rr[j], yB);
            }
            yA += __shfl_xor_sync(0xffffffffu, yA, 1);
            yB += __shfl_xor_sync(0xffffffffu, yB, 1);
            yA += __shfl_xor_sync(0xffffffffu, yA, 2);
            yB += __shfl_xor_sync(0xffffffffu, yB, 2);
            yA += __shfl_xor_sync(0xffffffffu, yA, 4);
            yB += __shfl_xor_sync(0xffffffffu, yB, 4);

            if (seg == 0) {
                const size_t yi = ybase + (size_t)t * Ddim;
                __nv_bfloat16 hiA = __float2bfloat16(yA);
                __nv_bfloat16 hiB = __float2bfloat16(yB);
                __nv_bfloat16 loA = __float2bfloat16(yA - __bfloat162float(hiA));
                __nv_bfloat16 loB = __float2bfloat16(yB - __bfloat162float(hiB));
                __nv_bfloat162 hp; hp.x = hiA; hp.y = hiB;
                __nv_bfloat162 lp; lp.x = loA; lp.y = loB;
                *(__nv_bfloat162*)&g_Ahi[yi] = hp;
                *(__nv_bfloat162*)&g_Alo[yi] = lp;
            }
        }
    }
}

// ---------------------------------------------------------------------------
// Kernel 2: mma.sync bf16 split GEMM (NT) — R5 config (2-stage, 96KB, 87us).
// 128x128 tile, BK=64, 8 warps (2x4), warp tile 64x32, SW128 swizzle.
// out[m,o] = scale[o] * (Ahi[m,:]+Alo[m,:]) . Wb[o,:]
// ---------------------------------------------------------------------------
#define NCH   (Ktot / 64)          // 32 K-chunks
#define STAGE 49152                // 3 tiles * 16KB
#define GSM_TOTAL (2 * STAGE)

__device__ __forceinline__ uint32_t swz(uint32_t row, uint32_t cbyte) {
    uint32_t off = row * 128 + cbyte;
    return off ^ ((off >> 3) & 0x70);
}

__global__ void __launch_bounds__(256) mma_gemm_kernel(
    const float* __restrict__ scale, float* __restrict__ out)
{
    extern __shared__ __align__(1024) char smem[];
    const uint32_t sb = smem_u32(smem);
    const int tid  = threadIdx.x;
    const int wid  = tid >> 5;
    const int lane = tid & 31;
    const int bm = blockIdx.y * 128;
    const int bn = blockIdx.x * 128;

    const int mbase = (wid >> 2) * 64;      // 0 / 64
    const int nbase = (wid & 3) * 32;       // 0/32/64/96

    auto load_stage = [&](int c, int p) {
        const uint32_t base = sb + p * STAGE;
        const size_t kof = (size_t)c * 64;
#pragma unroll
        for (int it = 0; it < 12; it++) {
            const int id   = tid + it * 256;        // 0..3071
            const int tile = id >> 10;              // 0:Ahi 1:Alo 2:W
            const int rem  = id & 1023;
            const int rw   = rem >> 3;              // row 0..127
            const int c8   = rem & 7;               // 16B chunk
            const uint32_t sa = base + tile * 16384 + swz(rw, c8 * 16);
            const __nv_bfloat16* g =
                (tile == 0) ? g_Ahi + (size_t)(bm + rw) * Ktot + kof + c8 * 8 :
                (tile == 1) ? g_Alo + (size_t)(bm + rw) * Ktot + kof + c8 * 8 :
                              g_Wb  + (size_t)(bn + rw) * Ktot + kof + c8 * 8;
            cp_async16(sa, g);
        }
    };

    float acc[4][4][4];
#pragma unroll
    for (int i = 0; i < 4; i++)
#pragma unroll
        for (int j = 0; j < 4; j++)
#pragma unroll
            for (int q = 0; q < 4; q++) acc[i][j][q] = 0.f;

    const uint32_t rowAl = lane & 15;
    const uint32_t cexA  = (lane >> 4) * 16;
    const uint32_t rowBl = ((lane >> 4) << 3) + (lane & 7);
    const uint32_t cexB  = ((lane >> 3) & 1) * 16;

    load_stage(0, 0);
    CP_COMMIT();

    for (int c = 0; c < NCH; c++) {
        const int p = c & 1;
        if (c + 1 < NCH) {
            load_stage(c + 1, p ^ 1);
            CP_COMMIT();
            CP_WAIT(1);
        } else {
            CP_WAIT(0);
        }
        __syncthreads();

        const uint32_t aB = sb + p * STAGE;          // Ahi
        const uint32_t lB = aB + 16384;               // Alo
        const uint32_t wB = aB + 32768;               // W

#pragma unroll
        for (int ks = 0; ks < 4; ks++) {
            const uint32_t kca = ks * 32 + cexA;
            const uint32_t kcb = ks * 32 + cexB;
            uint32_t bq[4][2];
            {
                uint32_t t[4];
                ldsm_x4(t, wB + swz(nbase + rowBl, kcb));
                bq[0][0] = t[0]; bq[0][1] = t[1]; bq[1][0] = t[2]; bq[1][1] = t[3];
                ldsm_x4(t, wB + swz(nbase + 16 + rowBl, kcb));
                bq[2][0] = t[0]; bq[2][1] = t[1]; bq[3][0] = t[2]; bq[3][1] = t[3];
            }
            uint32_t ah[4][4], al[4][4];
#pragma unroll
            for (int im = 0; im < 4; im++) {
                ldsm_x4(ah[im], aB + swz(mbase + im * 16 + rowAl, kca));
                ldsm_x4(al[im], lB + swz(mbase + im * 16 + rowAl, kca));
            }
#pragma unroll
            for (int im = 0; im < 4; im++)
#pragma unroll
                for (int in = 0; in < 4; in++) {
                    mma_bf16(acc[im][in], ah[im], bq[in]);
                    mma_bf16(acc[im][in], al[im], bq[in]);
                }
        }
        __syncthreads();
    }

    // ---- epilogue ----
    const int gid = lane >> 2;
    const int tig = lane & 3;
#pragma unroll
    for (int in = 0; in < 4; in++) {
        const int col = bn + nbase + in * 8 + tig * 2;
        const float s0 = scale[col], s1 = scale[col + 1];
#pragma unroll
        for (int im = 0; im < 4; im++) {
            const int row0 = bm + mbase + im * 16 + gid;
            float2 o0, o1;
            o0.x = acc[im][in][0] * s0; o0.y = acc[im][in][1] * s1;
            o1.x = acc[im][in][2] * s0; o1.y = acc[im][in][3] * s1;
            *(float2*)&out[(size_t)row0 * Ddim + col]       = o0;
            *(float2*)&out[(size_t)(row0 + 8) * Ddim + col] = o1;
        }
    }
}

// ---------------------------------------------------------------------------
extern "C" void kernel_launch(void* const* d_in, const int* in_sizes, int n_in,
                              void* d_out, int out_size)
{
    const float* r     = (const float*)d_in[0];
    const float* w     = (const float*)d_in[1];
    const float* k     = (const float*)d_in[2];
    const float* v     = (const float*)d_in[3];
    const float* iclr  = (const float*)d_in[4];
    const int*   wq    = (const int*)d_in[5];
    const float* wsc   = (const float*)d_in[6];
    float* out = (float*)d_out;

    wkv7_pre_kernel<<<Bdim * Tdim * Hdim / 8, 256>>>(w, k, iclr);
    wconv_kernel<<<(Ddim * Ktot) / 1024, 256>>>(wq);
    wkv7_scan_kernel<<<Bdim * Hdim, 256>>>(r, k, v);

    static int smem_set = 0;
    if (!smem_set) {
        cudaFuncSetAttribute(mma_gemm_kernel,
                             cudaFuncAttributeMaxDynamicSharedMemorySize, GSM_TOTAL);
        smem_set = 1;
    }
    dim3 grid(Ddim / 128, Mtot / 128);
    mma_gemm_kernel<<<grid, 256, GSM_TOTAL>>>(wsc, out);
}

// round 9
// speedup vs baseline: 2.5563x; 1.1129x over previous
#include <cuda_runtime.h>
#include <cuda_bf16.h>
#include <math.h>
#include <stdint.h>

#define Bdim 4
#define Tdim 512
#define Hdim 32
#define Ndim 64
#define Ddim 2048           // Hdim*Ndim
#define Mtot (Bdim*Tdim)    // 2048
#define Ktot Ddim           // 2048

typedef unsigned long long ull;

// ---------------- device scratch (no allocs allowed) ----------------
__device__ float          g_d [Bdim * Tdim * Ddim];   // decay
__device__ float          g_kk[Bdim * Tdim * Ddim];   // normalized k
__device__ float          g_bb[Bdim * Tdim * Ddim];   // kk * sigmoid(iclr)
__device__ __nv_bfloat16  g_Ahi[Mtot * Ktot];         // y hi (bf16)
__device__ __nv_bfloat16  g_Alo[Mtot * Ktot];         // y lo (bf16)
__device__ __nv_bfloat16  g_Wb [Ddim * Ktot];         // W (bf16, exact)

// ---------------- PTX helpers (plain sm_80+/sm_100 features only) --------
__device__ __forceinline__ uint32_t smem_u32(const void* p) {
    return (uint32_t)__cvta_generic_to_shared(p);
}
__device__ __forceinline__ void cp_async16(uint32_t smaddr, const void* g) {
    asm volatile("cp.async.cg.shared.global [%0], [%1], 16;" :: "r"(smaddr), "l"(g));
}
#define CP_COMMIT() asm volatile("cp.async.commit_group;" ::: "memory")
#define CP_WAIT(n)  asm volatile("cp.async.wait_group %0;" :: "n"(n) : "memory")

__device__ __forceinline__ void ldsm_x4(uint32_t* r, uint32_t addr) {
    asm volatile("ldmatrix.sync.aligned.m8n8.x4.shared.b16 {%0,%1,%2,%3}, [%4];"
        : "=r"(r[0]), "=r"(r[1]), "=r"(r[2]), "=r"(r[3]) : "r"(addr));
}
__device__ __forceinline__ void mma_bf16(float* d, const uint32_t* a, const uint32_t* b) {
    asm volatile("mma.sync.aligned.m16n8k16.row.col.f32.bf16.bf16.f32 "
        "{%0,%1,%2,%3}, {%4,%5,%6,%7}, {%8,%9}, {%0,%1,%2,%3};"
        : "+f"(d[0]), "+f"(d[1]), "+f"(d[2]), "+f"(d[3])
        : "r"(a[0]), "r"(a[1]), "r"(a[2]), "r"(a[3]), "r"(b[0]), "r"(b[1]));
}

// ---- packed f32x2 (sm_100+ plain PTX) ----
__device__ __forceinline__ ull pack2(float lo, float hi) {
    ull r; asm("mov.b64 %0, {%1, %2};" : "=l"(r) : "f"(lo), "f"(hi)); return r;
}
__device__ __forceinline__ void unpack2(ull v, float& lo, float& hi) {
    asm("mov.b64 {%0, %1}, %2;" : "=f"(lo), "=f"(hi) : "l"(v));
}
__device__ __forceinline__ ull fma2(ull a, ull b, ull c) {
    ull d; asm("fma.rn.f32x2 %0, %1, %2, %3;" : "=l"(d) : "l"(a), "l"(b), "l"(c));
    return d;
}
__device__ __forceinline__ ull mul2(ull a, ull b) {
    ull d; asm("mul.rn.f32x2 %0, %1, %2;" : "=l"(d) : "l"(a), "l"(b)); return d;
}

// ---------------------------------------------------------------------------
// Kernel 0a: elementwise precompute (decay, kk, b)
// ---------------------------------------------------------------------------
__global__ void __launch_bounds__(256) wkv7_pre_kernel(
    const float* __restrict__ w, const float* __restrict__ k,
    const float* __restrict__ iclr)
{
    const int vec  = blockIdx.x * 8 + (threadIdx.x >> 5);
    const int lane = threadIdx.x & 31;
    const size_t base = (size_t)vec * Ndim;

    float k0 = k[base + lane], k1 = k[base + lane + 32];
    float p = fmaf(k0, k0, k1 * k1);
#pragma unroll
    for (int o = 16; o; o >>= 1) p += __shfl_xor_sync(0xffffffffu, p, o);
    const float inv = rsqrtf(p + 1e-12f);

    float w0 = w[base + lane], w1 = w[base + lane + 32];
    float c0 = iclr[base + lane], c1 = iclr[base + lane + 32];

    g_d[base + lane]      = __expf(-__expf(w0));
    g_d[base + lane + 32] = __expf(-__expf(w1));
    const float kk0 = k0 * inv, kk1 = k1 * inv;
    g_kk[base + lane]      = kk0;
    g_kk[base + lane + 32] = kk1;
    g_bb[base + lane]      = kk0 / (1.0f + __expf(-c0));
    g_bb[base + lane + 32] = kk1 / (1.0f + __expf(-c1));
}

// ---------------------------------------------------------------------------
// Kernel 0b: Wq (int32) -> bf16 (exact, |v|<=128)
// ---------------------------------------------------------------------------
__global__ void __launch_bounds__(256) wconv_kernel(const int* __restrict__ wq)
{
    const size_t i4 = (size_t)blockIdx.x * 256 + threadIdx.x;   // int4 index
    int4 q = ((const int4*)wq)[i4];
    __nv_bfloat16 o[4];
    o[0] = __float2bfloat16((float)q.x);
    o[1] = __float2bfloat16((float)q.y);
    o[2] = __float2bfloat16((float)q.z);
    o[3] = __float2bfloat16((float)q.w);
    *(uint2*)&g_Wb[i4 * 4] = *(uint2*)o;
}

// ---------------------------------------------------------------------------
// Kernel 1: WKV scan. One block (256 thr) per (b,h).
// Layout: seg = tid&15 (4 cols each), rp = tid>>4 -> rows {4rp..4rp+3}.
// State: 4 rows x 4 cols = 8 f32x2 regs. Per step per thread: 6 LDS.128
// (5 operands + v float4) and ~44 packed f32x2 ops. Reductions: 4-stage
// shfl over 16 lanes. 8-slot cp.async ring, one commit group per 4-step
// superstep, ONE barrier per 4 steps.
// ---------------------------------------------------------------------------
__global__ void __launch_bounds__(256) wkv7_scan_kernel(
    const float* __restrict__ r, const float* __restrict__ k,
    const float* __restrict__ v)
{
    const int bh = blockIdx.x;          // 0..127
    const int b  = bh >> 5;
    const int h  = bh & 31;
    const int tid = threadIdx.x;
    const int seg = tid & 15;           // 0..15 (4-col segment)
    const int rp  = tid >> 4;           // 0..15 (row quad)
    const int row0 = rp * 4;
    const int jb  = seg * 4;            // column base

    // ring: 8 step-slots; slot layout:
    // d[0,64) kk[64,128) b[128,192) k[192,256) r[256,320) v[320,384)
    __shared__ __align__(16) float sbuf[8][6 * Ndim];

    ull st[4][2];
    const ull zero2 = pack2(0.f, 0.f);
#pragma unroll
    for (int i = 0; i < 4; i++) { st[i][0] = zero2; st[i][1] = zero2; }

    // loader mapping: lanes 0..11 of each warp -> 96 loaders, 1 float4 each
    const int wl   = tid >> 5;
    const int lane = tid & 31;
    const bool is_loader = (lane < 12);
    const int lidx = wl * 12 + lane;        // 0..95
    const int lvec = lidx >> 4;             // 0..5
    const int lq   = lidx & 15;             // 0..15
    const size_t vstep = (size_t)Hdim * Ndim / 4;   // float4 per t

    const float4* gbase = nullptr;
    uint32_t sdst = 0;
    if (is_loader) {
        const float* sp;
        switch (lvec) {
            case 0: sp = g_d;  break;
            case 1: sp = g_kk; break;
            case 2: sp = g_bb; break;
            case 3: sp = k;    break;
            case 4: sp = r;    break;
            default: sp = v;   break;
        }
        gbase = (const float4*)sp + (((size_t)b * Tdim) * Hdim + h) * (Ndim / 4) + lq;
        sdst  = smem_u32(&sbuf[0][0]) + lidx * 16;
    }
    const uint32_t slot_bytes = 6 * Ndim * 4;   // 1536

    // prologue: issue superstep 0 (steps 0..3)
    if (is_loader) {
#pragma unroll
        for (int u = 0; u < 4; u++)
            cp_async16(sdst + (u & 7) * slot_bytes, gbase + (size_t)u * vstep);
    }
    CP_COMMIT();

    const size_t ybase = ((size_t)b * Tdim) * Ddim + h * Ndim + row0;

    for (int t0 = 0; t0 < Tdim; t0 += 4) {
        CP_WAIT(0);                 // superstep t0 landed
        __syncthreads();

        // issue superstep t0+4 .. t0+7
        if (is_loader) {
#pragma unroll
            for (int u = 0; u < 4; u++) {
                const int st4 = t0 + 4 + u;
                if (st4 < Tdim)
                    cp_async16(sdst + (st4 & 7) * slot_bytes, gbase + (size_t)st4 * vstep);
            }
        }
        CP_COMMIT();

        // 4 compute steps, no barriers between them
#pragma unroll
        for (int u = 0; u < 4; u++) {
            const int t = t0 + u;
            const float* s = sbuf[t & 7];

            const ulonglong2 dv = *(const ulonglong2*)(s +   0 + jb);
            const ulonglong2 qv = *(const ulonglong2*)(s +  64 + jb);  // kk
            const ulonglong2 bv = *(const ulonglong2*)(s + 128 + jb);
            const ulonglong2 kv = *(const ulonglong2*)(s + 192 + jb);
            const ulonglong2 rv = *(const ulonglong2*)(s + 256 + jb);
            const float4 vv4 = *(const float4*)(s + 320 + row0);
            const float varr[4] = {vv4.x, vv4.y, vv4.z, vv4.w};

            // sa partials per row: dot(state_row_seg, kk_seg)
            float sap[4];
#pragma unroll
            for (int i = 0; i < 4; i++) {
                ull p = fma2(st[i][0], qv.x, mul2(st[i][1], qv.y));
                float plo, phi; unpack2(p, plo, phi);
                sap[i] = plo + phi;
            }
#pragma unroll
            for (int m = 1; m <= 8; m <<= 1) {
#pragma unroll
                for (int i = 0; i < 4; i++)
                    sap[i] += __shfl_xor_sync(0xffffffffu, sap[i], m);
            }

            // update + y partials
            float yp[4];
#pragma unroll
            for (int i = 0; i < 4; i++) {
                const ull sa2 = pack2(-sap[i], -sap[i]);
                const ull v2  = pack2(varr[i], varr[i]);
                ull t0p = fma2(sa2, bv.x, mul2(v2, kv.x));
                st[i][0] = fma2(st[i][0], dv.x, t0p);
                ull t1p = fma2(sa2, bv.y, mul2(v2, kv.y));
                st[i][1] = fma2(st[i][1], dv.y, t1p);
                ull ya = fma2(st[i][0], rv.x, fma2(st[i][1], rv.y, zero2));
                float ylo, yhi; unpack2(ya, ylo, yhi);
                yp[i] = ylo + yhi;
            }
#pragma unroll
            for (int m = 1; m <= 8; m <<= 1) {
#pragma unroll
                for (int i = 0; i < 4; i++)
                    yp[i] += __shfl_xor_sync(0xffffffffu, yp[i], m);
            }

            if (seg == 0) {
                const size_t yi = ybase + (size_t)t * Ddim;
                __nv_bfloat162 h0, h1, l0, l1;
                h0.x = __float2bfloat16(yp[0]);
                h0.y = __float2bfloat16(yp[1]);
                h1.x = __float2bfloat16(yp[2]);
                h1.y = __float2bfloat16(yp[3]);
                l0.x = __float2bfloat16(yp[0] - __bfloat162float(h0.x));
                l0.y = __float2bfloat16(yp[1] - __bfloat162float(h0.y));
                l1.x = __float2bfloat16(yp[2] - __bfloat162float(h1.x));
                l1.y = __float2bfloat16(yp[3] - __bfloat162float(h1.y));
                uint2 hu, lu;
                hu.x = *(uint32_t*)&h0; hu.y = *(uint32_t*)&h1;
                lu.x = *(uint32_t*)&l0; lu.y = *(uint32_t*)&l1;
                *(uint2*)&g_Ahi[yi] = hu;
                *(uint2*)&g_Alo[yi] = lu;
            }
        }
    }
}

// ---------------------------------------------------------------------------
// Kernel 2: mma.sync bf16 split GEMM (NT) — R5/R8 config (2-stage, 96KB, 87us).
// 128x128 tile, BK=64, 8 warps (2x4), warp tile 64x32, SW128 swizzle.
// out[m,o] = scale[o] * (Ahi[m,:]+Alo[m,:]) . Wb[o,:]
// ---------------------------------------------------------------------------
#define NCH   (Ktot / 64)          // 32 K-chunks
#define STAGE 49152                // 3 tiles * 16KB
#define GSM_TOTAL (2 * STAGE)

__device__ __forceinline__ uint32_t swz(uint32_t row, uint32_t cbyte) {
    uint32_t off = row * 128 + cbyte;
    return off ^ ((off >> 3) & 0x70);
}

__global__ void __launch_bounds__(256) mma_gemm_kernel(
    const float* __restrict__ scale, float* __restrict__ out)
{
    extern __shared__ __align__(1024) char smem[];
    const uint32_t sb = smem_u32(smem);
    const int tid  = threadIdx.x;
    const int wid  = tid >> 5;
    const int lane = tid & 31;
    const int bm = blockIdx.y * 128;
    const int bn = blockIdx.x * 128;

    const int mbase = (wid >> 2) * 64;      // 0 / 64
    const int nbase = (wid & 3) * 32;       // 0/32/64/96

    auto load_stage = [&](int c, int p) {
        const uint32_t base = sb + p * STAGE;
        const size_t kof = (size_t)c * 64;
#pragma unroll
        for (int it = 0; it < 12; it++) {
            const int id   = tid + it * 256;        // 0..3071
            const int tile = id >> 10;              // 0:Ahi 1:Alo 2:W
            const int rem  = id & 1023;
            const int rw   = rem >> 3;              // row 0..127
            const int c8   = rem & 7;               // 16B chunk
            const uint32_t sa = base + tile * 16384 + swz(rw, c8 * 16);
            const __nv_bfloat16* g =
                (tile == 0) ? g_Ahi + (size_t)(bm + rw) * Ktot + kof + c8 * 8 :
                (tile == 1) ? g_Alo + (size_t)(bm + rw) * Ktot + kof + c8 * 8 :
                              g_Wb  + (size_t)(bn + rw) * Ktot + kof + c8 * 8;
            cp_async16(sa, g);
        }
    };

    float acc[4][4][4];
#pragma unroll
    for (int i = 0; i < 4; i++)
#pragma unroll
        for (int j = 0; j < 4; j++)
#pragma unroll
            for (int q = 0; q < 4; q++) acc[i][j][q] = 0.f;

    const uint32_t rowAl = lane & 15;
    const uint32_t cexA  = (lane >> 4) * 16;
    const uint32_t rowBl = ((lane >> 4) << 3) + (lane & 7);
    const uint32_t cexB  = ((lane >> 3) & 1) * 16;

    load_stage(0, 0);
    CP_COMMIT();

    for (int c = 0; c < NCH; c++) {
        const int p = c & 1;
        if (c + 1 < NCH) {
            load_stage(c + 1, p ^ 1);
            CP_COMMIT();
            CP_WAIT(1);
        } else {
            CP_WAIT(0);
        }
        __syncthreads();

        const uint32_t aB = sb + p * STAGE;          // Ahi
        const uint32_t lB = aB + 16384;               // Alo
        const uint32_t wB = aB + 32768;               // W

#pragma unroll
        for (int ks = 0; ks < 4; ks++) {
            const uint32_t kca = ks * 32 + cexA;
            const uint32_t kcb = ks * 32 + cexB;
            uint32_t bq[4][2];
            {
                uint32_t t[4];
                ldsm_x4(t, wB + swz(nbase + rowBl, kcb));
                bq[0][0] = t[0]; bq[0][1] = t[1]; bq[1][0] = t[2]; bq[1][1] = t[3];
                ldsm_x4(t, wB + swz(nbase + 16 + rowBl, kcb));
                bq[2][0] = t[0]; bq[2][1] = t[1]; bq[3][0] = t[2]; bq[3][1] = t[3];
            }
            uint32_t ah[4][4], al[4][4];
#pragma unroll
            for (int im = 0; im < 4; im++) {
                ldsm_x4(ah[im], aB + swz(mbase + im * 16 + rowAl, kca));
                ldsm_x4(al[im], lB + swz(mbase + im * 16 + rowAl, kca));
            }
#pragma unroll
            for (int im = 0; im < 4; im++)
#pragma unroll
                for (int in = 0; in < 4; in++) {
                    mma_bf16(acc[im][in], ah[im], bq[in]);
                    mma_bf16(acc[im][in], al[im], bq[in]);
                }
        }
        __syncthreads();
    }

    // ---- epilogue ----
    const int gid = lane >> 2;
    const int tig = lane & 3;
#pragma unroll
    for (int in = 0; in < 4; in++) {
        const int col = bn + nbase + in * 8 + tig * 2;
        const float s0 = scale[col], s1 = scale[col + 1];
#pragma unroll
        for (int im = 0; im < 4; im++) {
            const int row0 = bm + mbase + im * 16 + gid;
            float2 o0, o1;
            o0.x = acc[im][in][0] * s0; o0.y = acc[im][in][1] * s1;
            o1.x = acc[im][in][2] * s0; o1.y = acc[im][in][3] * s1;
            *(float2*)&out[(size_t)row0 * Ddim + col]       = o0;
            *(float2*)&out[(size_t)(row0 + 8) * Ddim + col] = o1;
        }
    }
}

// ---------------------------------------------------------------------------
extern "C" void kernel_launch(void* const* d_in, const int* in_sizes, int n_in,
                              void* d_out, int out_size)
{
    const float* r     = (const float*)d_in[0];
    const float* w     = (const float*)d_in[1];
    const float* k     = (const float*)d_in[2];
    const float* v     = (const float*)d_in[3];
    const float* iclr  = (const float*)d_in[4];
    const int*   wq    = (const int*)d_in[5];
    const float* wsc   = (const float*)d_in[6];
    float* out = (float*)d_out;

    wkv7_pre_kernel<<<Bdim * Tdim * Hdim / 8, 256>>>(w, k, iclr);
    wconv_kernel<<<(Ddim * Ktot) / 1024, 256>>>(wq);
    wkv7_scan_kernel<<<Bdim * Hdim, 256>>>(r, k, v);

    static int smem_set = 0;
    if (!smem_set) {
        cudaFuncSetAttribute(mma_gemm_kernel,
                             cudaFuncAttributeMaxDynamicSharedMemorySize, GSM_TOTAL);
        smem_set = 1;
    }
    dim3 grid(Ddim / 128, Mtot / 128);
    mma_gemm_kernel<<<grid, 256, GSM_TOTAL>>>(wsc, out);
}

// round 10
// speedup vs baseline: 3.0751x; 1.2030x over previous
#include <cuda_runtime.h>
#include <cuda_bf16.h>
#include <math.h>
#include <stdint.h>

#define Bdim 4
#define Tdim 512
#define Hdim 32
#define Ndim 64
#define Ddim 2048           // Hdim*Ndim
#define Mtot (Bdim*Tdim)    // 2048
#define Ktot Ddim           // 2048

typedef unsigned long long ull;

// ---------------- device scratch (no allocs allowed) ----------------
__device__ float          g_d [Bdim * Tdim * Ddim];   // decay
__device__ float          g_kk[Bdim * Tdim * Ddim];   // normalized k
__device__ float          g_bb[Bdim * Tdim * Ddim];   // kk * sigmoid(iclr)
__device__ __nv_bfloat16  g_Ahi[Mtot * Ktot];         // y hi (bf16)
__device__ __nv_bfloat16  g_Alo[Mtot * Ktot];         // y lo (bf16)
__device__ __nv_bfloat16  g_Wb [Ddim * Ktot];         // W (bf16, exact)

// ---------------- PTX helpers (plain sm_80+/sm_100 features only) --------
__device__ __forceinline__ uint32_t smem_u32(const void* p) {
    return (uint32_t)__cvta_generic_to_shared(p);
}
__device__ __forceinline__ void cp_async16(uint32_t smaddr, const void* g) {
    asm volatile("cp.async.cg.shared.global [%0], [%1], 16;" :: "r"(smaddr), "l"(g));
}
#define CP_COMMIT() asm volatile("cp.async.commit_group;" ::: "memory")
#define CP_WAIT(n)  asm volatile("cp.async.wait_group %0;" :: "n"(n) : "memory")

__device__ __forceinline__ void ldsm_x4(uint32_t* r, uint32_t addr) {
    asm volatile("ldmatrix.sync.aligned.m8n8.x4.shared.b16 {%0,%1,%2,%3}, [%4];"
        : "=r"(r[0]), "=r"(r[1]), "=r"(r[2]), "=r"(r[3]) : "r"(addr));
}
__device__ __forceinline__ void mma_bf16(float* d, const uint32_t* a, const uint32_t* b) {
    asm volatile("mma.sync.aligned.m16n8k16.row.col.f32.bf16.bf16.f32 "
        "{%0,%1,%2,%3}, {%4,%5,%6,%7}, {%8,%9}, {%0,%1,%2,%3};"
        : "+f"(d[0]), "+f"(d[1]), "+f"(d[2]), "+f"(d[3])
        : "r"(a[0]), "r"(a[1]), "r"(a[2]), "r"(a[3]), "r"(b[0]), "r"(b[1]));
}

// ---- packed f32x2 (sm_100+ plain PTX) ----
__device__ __forceinline__ ull pack2(float lo, float hi) {
    ull r; asm("mov.b64 %0, {%1, %2};" : "=l"(r) : "f"(lo), "f"(hi)); return r;
}
__device__ __forceinline__ void unpack2(ull v, float& lo, float& hi) {
    asm("mov.b64 {%0, %1}, %2;" : "=f"(lo), "=f"(hi) : "l"(v));
}
__device__ __forceinline__ ull fma2(ull a, ull b, ull c) {
    ull d; asm("fma.rn.f32x2 %0, %1, %2, %3;" : "=l"(d) : "l"(a), "l"(b), "l"(c));
    return d;
}
__device__ __forceinline__ ull mul2(ull a, ull b) {
    ull d; asm("mul.rn.f32x2 %0, %1, %2;" : "=l"(d) : "l"(a), "l"(b)); return d;
}

// ---------------------------------------------------------------------------
// Kernel 0a: elementwise precompute (decay, kk, b)
// ---------------------------------------------------------------------------
__global__ void __launch_bounds__(256) wkv7_pre_kernel(
    const float* __restrict__ w, const float* __restrict__ k,
    const float* __restrict__ iclr)
{
    const int vec  = blockIdx.x * 8 + (threadIdx.x >> 5);
    const int lane = threadIdx.x & 31;
    const size_t base = (size_t)vec * Ndim;

    float k0 = k[base + lane], k1 = k[base + lane + 32];
    float p = fmaf(k0, k0, k1 * k1);
#pragma unroll
    for (int o = 16; o; o >>= 1) p += __shfl_xor_sync(0xffffffffu, p, o);
    const float inv = rsqrtf(p + 1e-12f);

    float w0 = w[base + lane], w1 = w[base + lane + 32];
    float c0 = iclr[base + lane], c1 = iclr[base + lane + 32];

    g_d[base + lane]      = __expf(-__expf(w0));
    g_d[base + lane + 32] = __expf(-__expf(w1));
    const float kk0 = k0 * inv, kk1 = k1 * inv;
    g_kk[base + lane]      = kk0;
    g_kk[base + lane + 32] = kk1;
    g_bb[base + lane]      = kk0 / (1.0f + __expf(-c0));
    g_bb[base + lane + 32] = kk1 / (1.0f + __expf(-c1));
}

// ---------------------------------------------------------------------------
// Kernel 0b: Wq (int32) -> bf16 (exact, |v|<=128)
// ---------------------------------------------------------------------------
__global__ void __launch_bounds__(256) wconv_kernel(const int* __restrict__ wq)
{
    const size_t i4 = (size_t)blockIdx.x * 256 + threadIdx.x;   // int4 index
    int4 q = ((const int4*)wq)[i4];
    __nv_bfloat16 o[4];
    o[0] = __float2bfloat16((float)q.x);
    o[1] = __float2bfloat16((float)q.y);
    o[2] = __float2bfloat16((float)q.z);
    o[3] = __float2bfloat16((float)q.w);
    *(uint2*)&g_Wb[i4 * 4] = *(uint2*)o;
}

// ---------------------------------------------------------------------------
// Kernel 1: WKV scan. One block (256 thr) per (b,h).
// Layout: seg = tid&15 (4 cols each), rp = tid>>4 -> rows {4rp..4rp+3}.
// sa allreduce: select-based reduce-scatter (5 shfl) + allgather (3 shfl).
// y reduction DEFERRED: per-step partials -> smem ybuf, reduced at the next
// superstep's barrier by all 256 threads (4 LDS.128 + adds + bf16 stores).
// 8-slot cp.async ring, one commit group per 4-step superstep.
// Dynamic smem: sbuf ring 12288 B + ybuf 2*4*64*20*4 = 40960 B = 53248 B.
// ---------------------------------------------------------------------------
#define SCAN_SMEM (8 * 6 * Ndim * 4 + 2 * 4 * 64 * 20 * 4)

__global__ void __launch_bounds__(256) wkv7_scan_kernel(
    const float* __restrict__ r, const float* __restrict__ k,
    const float* __restrict__ v)
{
    extern __shared__ __align__(16) float dsm[];
    float* sbuf = dsm;                       // [8][384]
    float* ybuf = dsm + 8 * 6 * Ndim;        // [2][4][64][20]

    const int bh = blockIdx.x;          // 0..127
    const int b  = bh >> 5;
    const int h  = bh & 31;
    const int tid = threadIdx.x;
    const int seg = tid & 15;           // 0..15 (4-col segment)
    const int rp  = tid >> 4;           // 0..15 (row quad)
    const int row0 = rp * 4;
    const int jb  = seg * 4;            // column base
    const int q0 = (seg >> 2) & 1;      // owned-row bits after reduce-scatter
    const int q1 = (seg >> 3) & 1;

    ull st[4][2];
    const ull zero2 = pack2(0.f, 0.f);
#pragma unroll
    for (int i = 0; i < 4; i++) { st[i][0] = zero2; st[i][1] = zero2; }

    // loader mapping: lanes 0..11 of each warp -> 96 loaders, 1 float4 each
    const int wl   = tid >> 5;
    const int lane = tid & 31;
    const bool is_loader = (lane < 12);
    const int lidx = wl * 12 + lane;        // 0..95
    const int lvec = lidx >> 4;             // 0..5
    const int lq   = lidx & 15;             // 0..15
    const size_t vstep = (size_t)Hdim * Ndim / 4;   // float4 per t

    const float4* gbase = nullptr;
    uint32_t sdst = 0;
    if (is_loader) {
        const float* sp;
        switch (lvec) {
            case 0: sp = g_d;  break;
            case 1: sp = g_kk; break;
            case 2: sp = g_bb; break;
            case 3: sp = k;    break;
            case 4: sp = r;    break;
            default: sp = v;   break;
        }
        gbase = (const float4*)sp + (((size_t)b * Tdim) * Hdim + h) * (Ndim / 4) + lq;
        sdst  = smem_u32(sbuf) + lidx * 16;
    }
    const uint32_t slot_bytes = 6 * Ndim * 4;   // 1536

    // y-reduction thread mapping (all 256 threads)
    const int ru   = tid >> 6;          // step-in-superstep 0..3
    const int rrow = tid & 63;          // row
    const size_t ybh = ((size_t)b * Tdim) * Ddim + h * Ndim;

    // prologue: issue superstep 0 (steps 0..3)
    if (is_loader) {
#pragma unroll
        for (int u = 0; u < 4; u++)
            cp_async16(sdst + (u & 7) * slot_bytes, gbase + (size_t)u * vstep);
    }
    CP_COMMIT();

    const int NSS = Tdim / 4;
    for (int ss = 0; ss < NSS; ss++) {
        const int t0 = ss * 4;
        CP_WAIT(0);                 // superstep t0 landed
        __syncthreads();

        // ---- reduce previous superstep's y partials ----
        if (ss > 0) {
            const float* yb = ybuf + (((ss - 1) & 1) * 4 + ru) * (64 * 20) + rrow * 20;
            float4 a0 = *(const float4*)(yb +  0);
            float4 a1 = *(const float4*)(yb +  4);
            float4 a2 = *(const float4*)(yb +  8);
            float4 a3 = *(const float4*)(yb + 12);
            float s = ((a0.x + a0.y) + (a0.z + a0.w))
                    + ((a1.x + a1.y) + (a1.z + a1.w))
                    + ((a2.x + a2.y) + (a2.z + a2.w))
                    + ((a3.x + a3.y) + (a3.z + a3.w));
            const size_t yi = ybh + (size_t)(t0 - 4 + ru) * Ddim + rrow;
            __nv_bfloat16 hi = __float2bfloat16(s);
            g_Ahi[yi] = hi;
            g_Alo[yi] = __float2bfloat16(s - __bfloat162float(hi));
        }

        // issue superstep t0+4 .. t0+7
        if (is_loader) {
#pragma unroll
            for (int u = 0; u < 4; u++) {
                const int st4 = t0 + 4 + u;
                if (st4 < Tdim)
                    cp_async16(sdst + (st4 & 7) * slot_bytes, gbase + (size_t)st4 * vstep);
            }
        }
        CP_COMMIT();

        float* ywb = ybuf + ((ss & 1) * 4) * (64 * 20);

        // 4 compute steps, no barriers between them
#pragma unroll
        for (int u = 0; u < 4; u++) {
            const int t = t0 + u;
            const float* s = sbuf + (t & 7) * (6 * Ndim);

            const ulonglong2 dv = *(const ulonglong2*)(s +   0 + jb);
            const ulonglong2 qv = *(const ulonglong2*)(s +  64 + jb);  // kk
            const ulonglong2 bv = *(const ulonglong2*)(s + 128 + jb);
            const ulonglong2 kv = *(const ulonglong2*)(s + 192 + jb);
            const ulonglong2 rv = *(const ulonglong2*)(s + 256 + jb);
            const float4 vv4 = *(const float4*)(s + 320 + row0);
            const float varr[4] = {vv4.x, vv4.y, vv4.z, vv4.w};

            // sa partials per row: dot(state_row_seg, kk_seg)
            float sap[4];
#pragma unroll
            for (int i = 0; i < 4; i++) {
                ull p = fma2(st[i][0], qv.x, mul2(st[i][1], qv.y));
                float plo, phi; unpack2(p, plo, phi);
                sap[i] = plo + phi;
            }

            // ---- allreduce of 4 values over 16 lanes: 8 shfl + selects ----
            // stage 1 (xor 8): rows {0,1} settle on bit3=0 lanes, {2,3} on bit3=1
            float s1a = q1 ? sap[0] : sap[2];
            float s1b = q1 ? sap[1] : sap[3];
            float r1  = __shfl_xor_sync(0xffffffffu, s1a, 8);
            float r2  = __shfl_xor_sync(0xffffffffu, s1b, 8);
            float m0  = (q1 ? sap[2] : sap[0]) + r1;
            float m1  = (q1 ? sap[3] : sap[1]) + r2;
            // stage 2 (xor 4): keep one value; owned row q = 2*q1 + q0
            float s2  = q0 ? m0 : m1;
            float r3  = __shfl_xor_sync(0xffffffffu, s2, 4);
            float val = (q0 ? m1 : m0) + r3;
            // stages 3,4: reduce over remaining 4 lanes
            val += __shfl_xor_sync(0xffffffffu, val, 2);
            val += __shfl_xor_sync(0xffffffffu, val, 1);
            // allgather: h_m = total of row q^m
            float g1 = __shfl_xor_sync(0xffffffffu, val, 4);   // row q^1
            float g2 = __shfl_xor_sync(0xffffffffu, val, 8);   // row q^2
            float g3 = __shfl_xor_sync(0xffffffffu, g1, 8);    // row q^3
            // permute back: X_j = h_{q^j}
            float a01 = q0 ? g1  : val;
            float a10 = q0 ? val : g1;
            float a23 = q0 ? g3  : g2;
            float a32 = q0 ? g2  : g3;
            float X0 = q1 ? a23 : a01;
            float X1 = q1 ? a32 : a10;
            float X2 = q1 ? a01 : a23;
            float X3 = q1 ? a10 : a32;
            const float saX[4] = {X0, X1, X2, X3};

            // update state + y partials -> smem
            float* yw = ywb + u * (64 * 20);
#pragma unroll
            for (int i = 0; i < 4; i++) {
                const ull sa2 = pack2(-saX[i], -saX[i]);
                const ull v2  = pack2(varr[i], varr[i]);
                ull t0p = fma2(sa2, bv.x, mul2(v2, kv.x));
                st[i][0] = fma2(st[i][0], dv.x, t0p);
                ull t1p = fma2(sa2, bv.y, mul2(v2, kv.y));
                st[i][1] = fma2(st[i][1], dv.y, t1p);
                ull ya = fma2(st[i][0], rv.x, fma2(st[i][1], rv.y, zero2));
                float ylo, yhi; unpack2(ya, ylo, yhi);
                yw[(row0 + i) * 20 + seg] = ylo + yhi;
            }
        }
    }

    // tail: reduce the last superstep's y
    __syncthreads();
    {
        const float* yb = ybuf + (((NSS - 1) & 1) * 4 + ru) * (64 * 20) + rrow * 20;
        float4 a0 = *(const float4*)(yb +  0);
        float4 a1 = *(const float4*)(yb +  4);
        float4 a2 = *(const float4*)(yb +  8);
        float4 a3 = *(const float4*)(yb + 12);
        float s = ((a0.x + a0.y) + (a0.z + a0.w))
                + ((a1.x + a1.y) + (a1.z + a1.w))
                + ((a2.x + a2.y) + (a2.z + a2.w))
                + ((a3.x + a3.y) + (a3.z + a3.w));
        const size_t yi = ybh + (size_t)(Tdim - 4 + ru) * Ddim + rrow;
        __nv_bfloat16 hi = __float2bfloat16(s);
        g_Ahi[yi] = hi;
        g_Alo[yi] = __float2bfloat16(s - __bfloat162float(hi));
    }
}

// ---------------------------------------------------------------------------
// Kernel 2: mma.sync bf16 split GEMM (NT). 2-stage, 96KB, now 2 CTAs/SM.
// 128x128 tile, BK=64, 8 warps (2x4), warp tile 64x32, SW128 swizzle.
// out[m,o] = scale[o] * (Ahi[m,:]+Alo[m,:]) . Wb[o,:]
// ---------------------------------------------------------------------------
#define NCH   (Ktot / 64)          // 32 K-chunks
#define STAGE 49152                // 3 tiles * 16KB
#define GSM_TOTAL (2 * STAGE)

__device__ __forceinline__ uint32_t swz(uint32_t row, uint32_t cbyte) {
    uint32_t off = row * 128 + cbyte;
    return off ^ ((off >> 3) & 0x70);
}

__global__ void __launch_bounds__(256, 2) mma_gemm_kernel(
    const float* __restrict__ scale, float* __restrict__ out)
{
    extern __shared__ __align__(1024) char smem[];
    const uint32_t sb = smem_u32(smem);
    const int tid  = threadIdx.x;
    const int wid  = tid >> 5;
    const int lane = tid & 31;
    const int bm = blockIdx.y * 128;
    const int bn = blockIdx.x * 128;

    const int mbase = (wid >> 2) * 64;      // 0 / 64
    const int nbase = (wid & 3) * 32;       // 0/32/64/96

    auto load_stage = [&](int c, int p) {
        const uint32_t base = sb + p * STAGE;
        const size_t kof = (size_t)c * 64;
#pragma unroll
        for (int it = 0; it < 12; it++) {
            const int id   = tid + it * 256;        // 0..3071
            const int tile = id >> 10;              // 0:Ahi 1:Alo 2:W
            const int rem  = id & 1023;
            const int rw   = rem >> 3;              // row 0..127
            const int c8   = rem & 7;               // 16B chunk
            const uint32_t sa = base + tile * 16384 + swz(rw, c8 * 16);
            const __nv_bfloat16* g =
                (tile == 0) ? g_Ahi + (size_t)(bm + rw) * Ktot + kof + c8 * 8 :
                (tile == 1) ? g_Alo + (size_t)(bm + rw) * Ktot + kof + c8 * 8 :
                              g_Wb  + (size_t)(bn + rw) * Ktot + kof + c8 * 8;
            cp_async16(sa, g);
        }
    };

    float acc[4][4][4];
#pragma unroll
    for (int i = 0; i < 4; i++)
#pragma unroll
        for (int j = 0; j < 4; j++)
#pragma unroll
            for (int q = 0; q < 4; q++) acc[i][j][q] = 0.f;

    const uint32_t rowAl = lane & 15;
    const uint32_t cexA  = (lane >> 4) * 16;
    const uint32_t rowBl = ((lane >> 4) << 3) + (lane & 7);
    const uint32_t cexB  = ((lane >> 3) & 1) * 16;

    load_stage(0, 0);
    CP_COMMIT();

    for (int c = 0; c < NCH; c++) {
        const int p = c & 1;
        if (c + 1 < NCH) {
            load_stage(c + 1, p ^ 1);
            CP_COMMIT();
            CP_WAIT(1);
        } else {
            CP_WAIT(0);
        }
        __syncthreads();

        const uint32_t aB = sb + p * STAGE;          // Ahi
        const uint32_t lB = aB + 16384;               // Alo
        const uint32_t wB = aB + 32768;               // W

#pragma unroll
        for (int ks = 0; ks < 4; ks++) {
            const uint32_t kca = ks * 32 + cexA;
            const uint32_t kcb = ks * 32 + cexB;
            uint32_t bq[4][2];
            {
                uint32_t t[4];
                ldsm_x4(t, wB + swz(nbase + rowBl, kcb));
                bq[0][0] = t[0]; bq[0][1] = t[1]; bq[1][0] = t[2]; bq[1][1] = t[3];
                ldsm_x4(t, wB + swz(nbase + 16 + rowBl, kcb));
                bq[2][0] = t[0]; bq[2][1] = t[1]; bq[3][0] = t[2]; bq[3][1] = t[3];
            }
            uint32_t ah[4][4], al[4][4];
#pragma unroll
            for (int im = 0; im < 4; im++) {
                ldsm_x4(ah[im], aB + swz(mbase + im * 16 + rowAl, kca));
                ldsm_x4(al[im], lB + swz(mbase + im * 16 + rowAl, kca));
            }
#pragma unroll
            for (int im = 0; im < 4; im++)
#pragma unroll
                for (int in = 0; in < 4; in++) {
                    mma_bf16(acc[im][in], ah[im], bq[in]);
                    mma_bf16(acc[im][in], al[im], bq[in]);
                }
        }
        __syncthreads();
    }

    // ---- epilogue ----
    const int gid = lane >> 2;
    const int tig = lane & 3;
#pragma unroll
    for (int in = 0; in < 4; in++) {
        const int col = bn + nbase + in * 8 + tig * 2;
        const float s0 = scale[col], s1 = scale[col + 1];
#pragma unroll
        for (int im = 0; im < 4; im++) {
            const int row0 = bm + mbase + im * 16 + gid;
            float2 o0, o1;
            o0.x = acc[im][in][0] * s0; o0.y = acc[im][in][1] * s1;
            o1.x = acc[im][in][2] * s0; o1.y = acc[im][in][3] * s1;
            *(float2*)&out[(size_t)row0 * Ddim + col]       = o0;
            *(float2*)&out[(size_t)(row0 + 8) * Ddim + col] = o1;
        }
    }
}

// ---------------------------------------------------------------------------
extern "C" void kernel_launch(void* const* d_in, const int* in_sizes, int n_in,
                              void* d_out, int out_size)
{
    const float* r     = (const float*)d_in[0];
    const float* w     = (const float*)d_in[1];
    const float* k     = (const float*)d_in[2];
    const float* v     = (const float*)d_in[3];
    const float* iclr  = (const float*)d_in[4];
    const int*   wq    = (const int*)d_in[5];
    const float* wsc   = (const float*)d_in[6];
    float* out = (float*)d_out;

    static int attr_set = 0;
    if (!attr_set) {
        cudaFuncSetAttribute(mma_gemm_kernel,
                             cudaFuncAttributeMaxDynamicSharedMemorySize, GSM_TOTAL);
        cudaFuncSetAttribute(wkv7_scan_kernel,
                             cudaFuncAttributeMaxDynamicSharedMemorySize, SCAN_SMEM);
        attr_set = 1;
    }

    wkv7_pre_kernel<<<Bdim * Tdim * Hdim / 8, 256>>>(w, k, iclr);
    wconv_kernel<<<(Ddim * Ktot) / 1024, 256>>>(wq);
    wkv7_scan_kernel<<<Bdim * Hdim, 256, SCAN_SMEM>>>(r, k, v);

    dim3 grid(Ddim / 128, Mtot / 128);
    mma_gemm_kernel<<<grid, 256, GSM_TOTAL>>>(wsc, out);
}